// round 4
// baseline (speedup 1.0000x reference)
#include <cuda_runtime.h>

// Shapes (fixed by the problem)
#define TT 2048
#define BB 1024
#define II 4
#define HH 10
#define OO 4

// sigmoid(x) = 1 / (1 + 2^(-x*log2e))          : FMUL + EX2 + FADD + RCP
__device__ __forceinline__ float fast_sigmoid(float x) {
    float e;
    asm("ex2.approx.f32 %0, %1;" : "=f"(e) : "f"(-1.4426950408889634f * x));
    float r;
    asm("rcp.approx.f32 %0, %1;" : "=f"(r) : "f"(1.0f + e));
    return r;
}

// tanh(x) = 1 - 2 / (1 + 2^(x*2*log2e))        : FMUL + EX2 + FADD + RCP + FMA
__device__ __forceinline__ float fast_tanh(float x) {
    float e;
    asm("ex2.approx.f32 %0, %1;" : "=f"(e) : "f"(2.8853900817779268f * x));
    float r;
    asm("rcp.approx.f32 %0, %1;" : "=f"(r) : "f"(1.0f + e));
    return fmaf(-2.0f, r, 1.0f);
}

// Layout: lane = (group, j). group = lane/10 in {0,1,2} (lanes 30,31 idle),
// j = hidden unit 0..9. batch = global_warp*3 + group.
// Each lane owns gate rows (i,f,g,o) for unit j in registers; h exchanged via shfl.
// FC output folded into the shuffle loop: out for step t-1 is computed while
// shuffling h_{t-1} for step t's gates (lanes j<4 each produce one output col).
__global__ void __launch_bounds__(128, 1)
lstm_fused(const float* __restrict__ x,
           const float* __restrict__ h0,
           const float* __restrict__ c0,
           const float* __restrict__ Wih,
           const float* __restrict__ Whh,
           const float* __restrict__ bih,
           const float* __restrict__ bhh,
           const float* __restrict__ Wfc,
           const float* __restrict__ bfc,
           float* __restrict__ out)
{
    const int lane = threadIdx.x & 31;
    const int warp = (blockIdx.x * blockDim.x + threadIdx.x) >> 5;
    const int grp  = lane / 10;            // 0..3 (3 == idle lanes 30,31)
    const int j    = lane - grp * 10;      // hidden unit, always < 10
    const int batch = warp * 3 + grp;
    const bool valid = (grp < 3) && (batch < BB);
    const int bl = valid ? batch : 0;      // clamped index for loads

    // ---- load weights into registers ----
    float wih[4][II], whh[4][HH], bias[4];
#pragma unroll
    for (int g = 0; g < 4; g++) {
        const int row = g * HH + j;        // PyTorch gate order i,f,g,o
        bias[g] = bih[row] + bhh[row];
#pragma unroll
        for (int i = 0; i < II; i++) wih[g][i] = Wih[row * II + i];
#pragma unroll
        for (int k = 0; k < HH; k++) whh[g][k] = Whh[row * HH + k];
    }
    float wfc[HH], bfcv;
    {
        const int o = (j < OO) ? j : 0;    // lanes j<4 produce output column j
#pragma unroll
        for (int k = 0; k < HH; k++) wfc[k] = Wfc[o * HH + k];
        bfcv = bfc[o];
    }

    float h = h0[bl * HH + j];
    float c = c0[bl * HH + j];

    // shuffle source lanes, hoisted out of the time loop
    int src[HH];
    const int base = grp * 10;
#pragma unroll
    for (int k = 0; k < HH; k++) src[k] = base + k;   // grp 3 wraps mod 32, harmless

    const bool do_out = valid && (j < OO);

    // depth-2 x prefetch: one broadcast float4 per batch per step
    float4 xbuf[2];
    const float4* xp = reinterpret_cast<const float4*>(x);
    xbuf[0] = xp[0 * BB + bl];
    xbuf[1] = xp[1 * BB + bl];

#pragma unroll 2
    for (int t = 0; t < TT; t++) {
        const float4 xv = xbuf[t & 1];
        const int tpre = (t + 2 < TT) ? (t + 2) : (TT - 1);
        xbuf[t & 1] = xp[tpre * BB + bl];

        // gate pre-activations: bias + W_ih @ x_t
        float a0 = fmaf(wih[0][0], xv.x, bias[0]);
        float a1 = fmaf(wih[1][0], xv.x, bias[1]);
        float a2 = fmaf(wih[2][0], xv.x, bias[2]);
        float a3 = fmaf(wih[3][0], xv.x, bias[3]);
        a0 = fmaf(wih[0][1], xv.y, a0);
        a1 = fmaf(wih[1][1], xv.y, a1);
        a2 = fmaf(wih[2][1], xv.y, a2);
        a3 = fmaf(wih[3][1], xv.y, a3);
        a0 = fmaf(wih[0][2], xv.z, a0);
        a1 = fmaf(wih[1][2], xv.z, a1);
        a2 = fmaf(wih[2][2], xv.z, a2);
        a3 = fmaf(wih[3][2], xv.z, a3);
        a0 = fmaf(wih[0][3], xv.w, a0);
        a1 = fmaf(wih[1][3], xv.w, a1);
        a2 = fmaf(wih[2][3], xv.w, a2);
        a3 = fmaf(wih[3][3], xv.w, a3);

        // + W_hh @ h_{t-1}; simultaneously FC output for step t-1
        float ao = bfcv;
#pragma unroll
        for (int k = 0; k < HH; k++) {
            const float hk = __shfl_sync(0xffffffffu, h, src[k]);
            a0 = fmaf(whh[0][k], hk, a0);
            a1 = fmaf(whh[1][k], hk, a1);
            a2 = fmaf(whh[2][k], hk, a2);
            a3 = fmaf(whh[3][k], hk, a3);
            ao = fmaf(wfc[k], hk, ao);
        }
        if (do_out && t > 0)
            out[((t - 1) * BB + batch) * OO + j] = ao;

        const float ig = fast_sigmoid(a0);
        const float fg = fast_sigmoid(a1);
        const float gg = fast_tanh(a2);
        const float og = fast_sigmoid(a3);
        c = fmaf(fg, c, ig * gg);
        h = og * fast_tanh(c);
    }

    // tail: FC output for the final step
    {
        float ao = bfcv;
#pragma unroll
        for (int k = 0; k < HH; k++) {
            const float hk = __shfl_sync(0xffffffffu, h, src[k]);
            ao = fmaf(wfc[k], hk, ao);
        }
        if (do_out)
            out[((TT - 1) * BB + batch) * OO + j] = ao;
    }

    // final states hT, cT appended after out: [B,H] each
    if (valid) {
        out[TT * BB * OO + batch * HH + j] = h;
        out[TT * BB * OO + BB * HH + batch * HH + j] = c;
    }
}

extern "C" void kernel_launch(void* const* d_in, const int* in_sizes, int n_in,
                              void* d_out, int out_size) {
    const float* x   = (const float*)d_in[0];
    const float* h0  = (const float*)d_in[1];
    const float* c0  = (const float*)d_in[2];
    const float* Wih = (const float*)d_in[3];
    const float* Whh = (const float*)d_in[4];
    const float* bih = (const float*)d_in[5];
    const float* bhh = (const float*)d_in[6];
    const float* Wfc = (const float*)d_in[7];
    const float* bfc = (const float*)d_in[8];

    // 342 warps (3 batches each) -> 86 blocks of 4 warps; every warp runs
    // alone on an SMSP, fully warp-synchronous (no barriers, no smem).
    lstm_fused<<<86, 128>>>(x, h0, c0, Wih, Whh, bih, bhh, Wfc, bfc,
                            (float*)d_out);
}